// round 16
// baseline (speedup 1.0000x reference)
#include <cuda_runtime.h>
#include <cuda_fp16.h>

// Problem constants
#define TT    1024   // seq len
#define BB    1024   // batch
#define HH    64     // encoder hidden
#define NBC   8      // batches per CTA (4 per subgroup; clamped dups at end)
#define CTAS  148    // all SMs busy; 148*8 = 1184 >= 1024

// ---------------------------------------------------------------------------
// helpers
// ---------------------------------------------------------------------------
__device__ __forceinline__ float tanhapx(float x) {    // MUFU.TANH
    float r; asm("tanh.approx.f32 %0, %1;" : "=r"(*(unsigned*)&r) : "f"(x));
    return r;
}
__device__ __forceinline__ unsigned h2pack(float a, float b) {
    __half2 h = __floats2half2_rn(a, b);
    return *(unsigned*)&h;
}
__device__ __forceinline__ void mma_f16(float& c0, float& c1, float& c2, float& c3,
                                        unsigned a0, unsigned a1, unsigned a2, unsigned a3,
                                        unsigned b0, unsigned b1) {
    asm("mma.sync.aligned.m16n8k16.row.col.f32.f16.f16.f32 "
        "{%0,%1,%2,%3},{%4,%5,%6,%7},{%8,%9},{%0,%1,%2,%3};"
        : "+f"(c0), "+f"(c1), "+f"(c2), "+f"(c3)
        : "r"(a0), "r"(a1), "r"(a2), "r"(a3), "r"(b0), "r"(b1));
}
__device__ __forceinline__ float sel4(float v0, float v1, float v2, float v3, int k) {
    float a = (k & 1) ? v1 : v0;
    float b = (k & 1) ? v3 : v2;
    return (k & 2) ? b : a;
}

#define HSTR 36   // word stride of one batch's h row (32 half2 words + pad)

// ---------------------------------------------------------------------------
// Fused encoder+decoder, fp16 m16n8k16 tensor cores, 512 threads.
//
// Two 256-thread subgroups (sg = tid>>8) with INDEPENDENT named barriers so
// their matvec/epilogue phases drift and interleave on every SMSP (4 warps/
// SMSP). Subgroup sg owns real batches b0 + 4sg + {0..3}; mma n-slots 4-7
// duplicate them (clamped x) -- deterministic, and tensor util stays low.
//
// Warp layout (validated in R14/15): warp wl owns the permuted 32-row
// A-tile = all 4 gates of j in [8wl, 8wl+8); lane gi=(lane>>2)&3 is the
// gate of its C rows; i/f/g/o combine is warp-local (3 shfl_xor + selects).
// Weights as fp16 half2 (k-pairs), h as half2 in slot-permuted SMEM rows
// (one LDS.64 per B fragment). Activation scale (sigmoid 1/2-fold) per R15;
// fp32 accumulators, bias + x-term fp32. Producer lanes pair j/j+1 h values
// via one shfl_xor(16); J==0 lanes store half2.
// One named barrier per subgroup per step; exact fp32 h saved at t=1023.
// Decoder (hidden=1, tanh.approx) fused: 8 threads per CTA.
// ---------------------------------------------------------------------------
__global__ void __launch_bounds__(512, 1) fused_kernel(
    const float* __restrict__ x,      // [T, B, 1]
    const float* __restrict__ Wih,    // [256, 1]
    const float* __restrict__ Whh,    // [256, 64]
    const float* __restrict__ bih,    // [256]
    const float* __restrict__ bhh,    // [256]
    const float* __restrict__ Wih_d,  // [4, 64]
    const float* __restrict__ Whh_d,  // [4, 1]
    const float* __restrict__ bih_d,  // [4]
    const float* __restrict__ bhh_d,  // [4]
    float* __restrict__ out)          // [T, B, 1]
{
    const int tid  = threadIdx.x;
    const int sg   = tid >> 8;            // subgroup 0/1
    const int wl   = (tid >> 5) & 7;      // warp in subgroup
    const int lane = tid & 31;
    const int gi   = (lane >> 2) & 3;     // my C-rows' gate
    const int J    = lane >> 4;           // 0/1
    const int n0   = 2 * (lane & 3);      // my C-fragment n pair
    const int b0   = blockIdx.x * NBC;

    __shared__ __align__(16) unsigned hsm[2][2][8][HSTR]; // [sg][p][n][slot]
    __shared__ __align__(16) float xs[2][2][8];           // [sg][p][n]
    __shared__ __align__(16) float hfin[8][HH];           // exact final h

    // activation parametrization (gi==2 tanh; sigmoid via 0.5+0.5*tanh(v/2))
    const float s  = (gi == 2) ? 1.0f : 0.5f;
    const float Am = (gi == 2) ? 1.0f : 0.5f;
    const float Bm = (gi == 2) ? 0.0f : 0.5f;

    // ---- A weights: 2 m-tiles x 4 k16-tiles x 4 half2 regs, scale folded --
    unsigned wa[2][4][4];
    #pragma unroll
    for (int T = 0; T < 2; T++) {
        const int jA = 8 * wl + J + 4 * T;
        const int r0 = gi * HH + jA;
        const int r1 = r0 + 2;
        #pragma unroll
        for (int kt = 0; kt < 4; kt++) {
            const int k0 = 16 * kt + 2 * (lane & 3);
            wa[T][kt][0] = h2pack(s * Whh[r0 * HH + k0],     s * Whh[r0 * HH + k0 + 1]);
            wa[T][kt][1] = h2pack(s * Whh[r1 * HH + k0],     s * Whh[r1 * HH + k0 + 1]);
            wa[T][kt][2] = h2pack(s * Whh[r0 * HH + k0 + 8], s * Whh[r0 * HH + k0 + 9]);
            wa[T][kt][3] = h2pack(s * Whh[r1 * HH + k0 + 8], s * Whh[r1 * HH + k0 + 9]);
        }
    }
    float bs[4], ws[4];
    #pragma unroll
    for (int m = 0; m < 4; m++) {
        const int row = gi * HH + 8 * wl + J + 2 * m;
        bs[m] = s * (bih[row] + bhh[row]);
        ws[m] = s * Wih[row];
    }

    // owned items + h-store slot (word q = 4wl + gi holds j pair 2q, 2q+1)
    const int jj_own = 2 * gi + J;
    const int jmine  = 8 * wl + jj_own;
    const int q      = 4 * wl + gi;
    const int u      = q & 7;
    const int slot   = 8 * (q >> 3) + 2 * (u & 3) + (u >> 2);

    // per-thread x-loader role (lanes 0-7 of warp 0 of each subgroup)
    const bool xldr = ((tid & 255) < 8);
    int gbx = 0;
    if (xldr) {
        int n = tid & 7;
        gbx = b0 + sg * 4 + (n & 3); if (gbx > BB - 1) gbx = BB - 1;
    }

    // init h = 0 (both buffers), x stage for t=0
    for (int i = tid; i < 2 * 2 * 8 * HSTR; i += 512) ((unsigned*)hsm)[i] = 0u;
    if (xldr) xs[sg][0][tid & 7] = x[gbx];
    float cc[2] = {0.0f, 0.0f};
    __syncthreads();

    for (int t = 0; t < TT; t++) {
        const int p = t & 1;

        // x for my n pair + early prefetch of next step's x
        float2 xx = *(const float2*)&xs[sg][p][n0];
        float xpre = 0.0f;
        if (xldr && (t + 1 < TT)) xpre = __ldg(&x[(t + 1) * BB + gbx]);

        // B fragments (h of this step): 4 x LDS.64
        const unsigned* hb = &hsm[sg][p][lane >> 2][0];
        uint2 bb[4];
        #pragma unroll
        for (int kt = 0; kt < 4; kt++)
            bb[kt] = *(const uint2*)&hb[8 * kt + 2 * (lane & 3)];

        // accumulators: A (kt0-1) init bias+x, B (kt2-3) init 0
        float aA[2][4], aB[2][4];
        #pragma unroll
        for (int T = 0; T < 2; T++)
            #pragma unroll
            for (int qq = 0; qq < 4; qq++) {
                const int m = 2 * T + (qq >> 1);
                aA[T][qq] = fmaf(ws[m], (qq & 1) ? xx.y : xx.x, bs[m]);
                aB[T][qq] = 0.0f;
            }

        // 8 mma.sync as 4 depth-2 chains
        #pragma unroll
        for (int T = 0; T < 2; T++) {
            mma_f16(aA[T][0], aA[T][1], aA[T][2], aA[T][3],
                    wa[T][0][0], wa[T][0][1], wa[T][0][2], wa[T][0][3], bb[0].x, bb[0].y);
            mma_f16(aB[T][0], aB[T][1], aB[T][2], aB[T][3],
                    wa[T][2][0], wa[T][2][1], wa[T][2][2], wa[T][2][3], bb[2].x, bb[2].y);
            mma_f16(aA[T][0], aA[T][1], aA[T][2], aA[T][3],
                    wa[T][1][0], wa[T][1][1], wa[T][1][2], wa[T][1][3], bb[1].x, bb[1].y);
            mma_f16(aB[T][0], aB[T][1], aB[T][2], aB[T][3],
                    wa[T][3][0], wa[T][3][1], wa[T][3][2], wa[T][3][3], bb[3].x, bb[3].y);
        }

        // activations: one tanh.approx each
        float act[4][2];
        #pragma unroll
        for (int T = 0; T < 2; T++)
            #pragma unroll
            for (int qq = 0; qq < 4; qq++) {
                const int m  = 2 * T + (qq >> 1);
                const int ns = qq & 1;
                act[m][ns] = fmaf(Am, tanhapx(aA[T][qq] + aB[T][qq]), Bm);
            }

        // warp-local 4-gate gather + c/h update for my 2 items
        #pragma unroll
        for (int ns = 0; ns < 2; ns++) {
            float s1 = sel4(act[0][ns], act[1][ns], act[2][ns], act[3][ns], gi ^ 1);
            float s2 = sel4(act[0][ns], act[1][ns], act[2][ns], act[3][ns], gi ^ 2);
            float s3 = sel4(act[0][ns], act[1][ns], act[2][ns], act[3][ns], gi ^ 3);
            float r0 = sel4(act[0][ns], act[1][ns], act[2][ns], act[3][ns], gi);
            float r1 = __shfl_xor_sync(0xffffffffu, s1, 4);
            float r2 = __shfl_xor_sync(0xffffffffu, s2, 8);
            float r3 = __shfl_xor_sync(0xffffffffu, s3, 12);
            float vi = sel4(r0, r1, r2, r3, gi);
            float vf = sel4(r0, r1, r2, r3, gi ^ 1);
            float vg = sel4(r0, r1, r2, r3, gi ^ 2);
            float vo = sel4(r0, r1, r2, r3, gi ^ 3);
            cc[ns] = fmaf(vf, cc[ns], vi * vg);
            float hn = vo * tanhapx(cc[ns]);

            // pair j (J=0) with j+1 (J=1) and store one half2 word
            float hpart = __shfl_xor_sync(0xffffffffu, hn, 16);
            if (J == 0) hsm[sg][p ^ 1][n0 + ns][slot] = h2pack(hn, hpart);
            if ((t == TT - 1) && (n0 + ns) < 4) hfin[sg * 4 + n0 + ns][jmine] = hn;
        }

        if (xldr && (t + 1 < TT)) xs[sg][p ^ 1][tid & 7] = xpre;

        // per-subgroup barrier -> subgroups drift independently
        asm volatile("bar.sync %0, %1;" :: "r"(sg + 1), "r"(256) : "memory");
    }
    __syncthreads();   // decoder reads both subgroups' hfin

    // ------------------- fused decoder (8 threads per CTA) -------------------
    if (tid < NBC) {
        const float* he = hfin[tid];
        int gb = b0 + tid; if (gb > BB - 1) gb = BB - 1;  // dup: identical chain
        float z[4], wd[4];
        #pragma unroll
        for (int g = 0; g < 4; g++) {
            float acc = bih_d[g] + bhh_d[g];
            const float* wr = Wih_d + g * HH;
            #pragma unroll 8
            for (int k = 0; k < HH; k++) acc = fmaf(wr[k], he[k], acc);
            const float sd = (g == 2) ? 1.0f : 0.5f;
            z[g]  = sd * acc;
            wd[g] = sd * Whh_d[g];
        }
        float h = 0.0f, c = 0.0f;
        float* op = out + gb;
        for (int t = 0; t < TT; t++) {
            float ai = fmaf(0.5f, tanhapx(fmaf(wd[0], h, z[0])), 0.5f);
            float af = fmaf(0.5f, tanhapx(fmaf(wd[1], h, z[1])), 0.5f);
            float ag = tanhapx(fmaf(wd[2], h, z[2]));
            float ao = fmaf(0.5f, tanhapx(fmaf(wd[3], h, z[3])), 0.5f);
            c = fmaf(af, c, ai * ag);
            h = ao * tanhapx(c);
            *op = h;           // clamped duplicates race with identical values
            op += BB;
        }
    }
}

// ---------------------------------------------------------------------------
// launch
// ---------------------------------------------------------------------------
extern "C" void kernel_launch(void* const* d_in, const int* in_sizes, int n_in,
                              void* d_out, int out_size) {
    const float* x     = (const float*)d_in[0];
    const float* Wih_e = (const float*)d_in[1];
    const float* Whh_e = (const float*)d_in[2];
    const float* bih_e = (const float*)d_in[3];
    const float* bhh_e = (const float*)d_in[4];
    const float* Wih_d = (const float*)d_in[5];
    const float* Whh_d = (const float*)d_in[6];
    const float* bih_d = (const float*)d_in[7];
    const float* bhh_d = (const float*)d_in[8];
    float* out = (float*)d_out;

    fused_kernel<<<CTAS, 512>>>(x, Wih_e, Whh_e, bih_e, bhh_e,
                                Wih_d, Whh_d, bih_d, bhh_d, out);
}

// round 17
// speedup vs baseline: 1.5819x; 1.5819x over previous
#include <cuda_runtime.h>
#include <cuda_fp16.h>

// Problem constants
#define TT    1024   // seq len
#define BB    1024   // batch
#define HH    64     // encoder hidden
#define NBR   7      // batch stride per CTA (8 n-slots; slot7 dups next CTA's b0)
#define CTAS  148    // all SMs busy; 148*7 = 1036 >= 1024

// ---------------------------------------------------------------------------
// helpers
// ---------------------------------------------------------------------------
__device__ __forceinline__ float tanhapx(float x) {    // MUFU.TANH
    float r; asm("tanh.approx.f32 %0, %1;" : "=r"(*(unsigned*)&r) : "f"(x));
    return r;
}
__device__ __forceinline__ unsigned h2pack(float a, float b) {
    __half2 h = __floats2half2_rn(a, b);
    return *(unsigned*)&h;
}
__device__ __forceinline__ void mma_f16(float& c0, float& c1, float& c2, float& c3,
                                        unsigned a0, unsigned a1, unsigned a2, unsigned a3,
                                        unsigned b0, unsigned b1) {
    asm("mma.sync.aligned.m16n8k16.row.col.f32.f16.f16.f32 "
        "{%0,%1,%2,%3},{%4,%5,%6,%7},{%8,%9},{%0,%1,%2,%3};"
        : "+f"(c0), "+f"(c1), "+f"(c2), "+f"(c3)
        : "r"(a0), "r"(a1), "r"(a2), "r"(a3), "r"(b0), "r"(b1));
}

#define HSTR 36   // word stride of one n's h row (32 half2 words + pad)

// ---------------------------------------------------------------------------
// Fused encoder+decoder, fp16 m16n8k16, GATHER-FREE C layout.
//
// A-row permutation chosen so each thread's C fragment holds ALL FOUR gates
// of one (j, n-pair):
//   m-tile 0: logical row g       = gate i of j = 8w+g   (physical row j)
//             logical row g+8     = gate f of j           (row 64+j)
//   m-tile 1: logical row g       = gate g~ of j          (row 128+j)
//             logical row g+8     = gate o of j           (row 192+j)
// (A frag: a0/a2 = logical row groupID, a1/a3 = groupID+8; C frag: c0,c1 =
// row groupID @ cols 2tig,2tig+1, c2,c3 = row groupID+8 — so thread
// (groupID=lane>>2, tig=lane&3) owns gates {i,f} (tile0) + {g,o} (tile1) of
// j = 8w+groupID at n = 2tig, 2tig+1.)
// => the cross-gate combine is LOCAL: zero shuffles/selects, and the
// activation constants are compile-time per C register.
//
// Epilogue per thread: 8 tanh.approx acts (sigmoid = 0.5+0.5*tanh(v/2),
// scale folded into weights/bias), 2 c/h chains, one shfl_xor(4) pairing
// h_j with h_{j^1}, even-j lanes store half2 into the slot-permuted h rows
// (same layout as validated R16: consumer B-frag = one LDS.64 per k-tile).
// 148 CTAs x 256 thr; batches b0+{0..7} with clamped tail (slot7 duplicates
// the next CTA's first chain bit-identically -- benign race, proven R15).
// One __syncthreads per step; exact fp32 h saved at t=1023 for the decoder.
// ---------------------------------------------------------------------------
__global__ void __launch_bounds__(256, 1) fused_kernel(
    const float* __restrict__ x,      // [T, B, 1]
    const float* __restrict__ Wih,    // [256, 1]
    const float* __restrict__ Whh,    // [256, 64]
    const float* __restrict__ bih,    // [256]
    const float* __restrict__ bhh,    // [256]
    const float* __restrict__ Wih_d,  // [4, 64]
    const float* __restrict__ Whh_d,  // [4, 1]
    const float* __restrict__ bih_d,  // [4]
    const float* __restrict__ bhh_d,  // [4]
    float* __restrict__ out)          // [T, B, 1]
{
    const int tid  = threadIdx.x;
    const int w    = tid >> 5;
    const int lane = tid & 31;
    const int gid  = lane >> 2;           // C row group = my j offset
    const int tig  = lane & 3;
    const int j    = 8 * w + gid;         // my hidden index
    const int n0   = 2 * tig;             // my n pair
    const int b0   = blockIdx.x * NBR;

    __shared__ __align__(16) unsigned hsm[2][8][HSTR]; // [p][n][slot] half2 h
    __shared__ __align__(16) float xs[2][8];           // x stage
    __shared__ __align__(16) float hfin[8][HH];        // exact final h

    // ---- A weights: tile T rows = gates {2T, 2T+1} of j; scale folded ----
    // gate scales: sigmoid gates (0,1,3) -> 1/2 fold; tanh gate (2) -> 1
    unsigned wa[2][4][4];
    #pragma unroll
    for (int T = 0; T < 2; T++) {
        const int   gA = 2 * T, gB = 2 * T + 1;
        const float sA = (gA == 2) ? 1.0f : 0.5f;
        const float sB = 0.5f;                       // gates 1,3 are sigmoid
        const float* rA = Whh + (gA * HH + j) * HH;
        const float* rB = Whh + (gB * HH + j) * HH;
        #pragma unroll
        for (int kt = 0; kt < 4; kt++) {
            const int k0 = 16 * kt + 2 * tig;
            wa[T][kt][0] = h2pack(sA * rA[k0],     sA * rA[k0 + 1]);
            wa[T][kt][1] = h2pack(sB * rB[k0],     sB * rB[k0 + 1]);
            wa[T][kt][2] = h2pack(sA * rA[k0 + 8], sA * rA[k0 + 9]);
            wa[T][kt][3] = h2pack(sB * rB[k0 + 8], sB * rB[k0 + 9]);
        }
    }
    float bs[4], ws4[4];
    #pragma unroll
    for (int G = 0; G < 4; G++) {
        const float sG = (G == 2) ? 1.0f : 0.5f;
        const int row  = G * HH + j;
        bs[G]  = sG * (bih[row] + bhh[row]);
        ws4[G] = sG * Wih[row];
    }

    // h-store slot: word kw = j>>1; permute so (kw, kw+4) land adjacent
    const int kw   = j >> 1;
    const int u    = kw & 7;
    const int slot = 8 * (kw >> 3) + 2 * (u & 3) + (u >> 2);

    // x loader role
    int gbx = 0;
    if (tid < 8) { gbx = b0 + tid; if (gbx > BB - 1) gbx = BB - 1; }

    // init: h = 0 (both buffers), x stage for t=0
    for (int i = tid; i < 2 * 8 * HSTR; i += 256) ((unsigned*)hsm)[i] = 0u;
    if (tid < 8) xs[0][tid] = x[gbx];
    float cc[2] = {0.0f, 0.0f};
    __syncthreads();

    for (int t = 0; t < TT; t++) {
        const int p = t & 1;

        // x for my n pair (LDS.64) + early prefetch of next step's x
        float2 xx = *(const float2*)&xs[p][n0];
        float xpre = 0.0f;
        if ((tid < 8) && (t + 1 < TT)) xpre = __ldg(&x[(t + 1) * BB + gbx]);

        // B fragments (h of this step): 4 x LDS.64, row n = gid
        const unsigned* hb = &hsm[p][gid][0];
        uint2 bb[4];
        #pragma unroll
        for (int kt = 0; kt < 4; kt++)
            bb[kt] = *(const uint2*)&hb[8 * kt + 2 * tig];

        // accumulators: A (kt0-1) init bias+x, B (kt2-3) init 0
        float aA[2][4], aB[2][4];
        #pragma unroll
        for (int T = 0; T < 2; T++)
            #pragma unroll
            for (int q = 0; q < 4; q++) {
                const int G  = 2 * T + (q >> 1);
                aA[T][q] = fmaf(ws4[G], (q & 1) ? xx.y : xx.x, bs[G]);
                aB[T][q] = 0.0f;
            }

        // 8 mma.sync as 4 depth-2 chains
        #pragma unroll
        for (int T = 0; T < 2; T++) {
            mma_f16(aA[T][0], aA[T][1], aA[T][2], aA[T][3],
                    wa[T][0][0], wa[T][0][1], wa[T][0][2], wa[T][0][3], bb[0].x, bb[0].y);
            mma_f16(aB[T][0], aB[T][1], aB[T][2], aB[T][3],
                    wa[T][2][0], wa[T][2][1], wa[T][2][2], wa[T][2][3], bb[2].x, bb[2].y);
            mma_f16(aA[T][0], aA[T][1], aA[T][2], aA[T][3],
                    wa[T][1][0], wa[T][1][1], wa[T][1][2], wa[T][1][3], bb[1].x, bb[1].y);
            mma_f16(aB[T][0], aB[T][1], aB[T][2], aB[T][3],
                    wa[T][3][0], wa[T][3][1], wa[T][3][2], wa[T][3][3], bb[3].x, bb[3].y);
        }

        // activations (compile-time constants per C register) -- all LOCAL
        float act[4][2];
        #pragma unroll
        for (int T = 0; T < 2; T++)
            #pragma unroll
            for (int q = 0; q < 4; q++) {
                const int G  = 2 * T + (q >> 1);
                const int ns = q & 1;
                const float v = aA[T][q] + aB[T][q];
                act[G][ns] = (G == 2) ? tanhapx(v)
                                      : fmaf(0.5f, tanhapx(v), 0.5f);
            }

        // gather-free c/h update for my 2 items (all 4 gates already local)
        #pragma unroll
        for (int ns = 0; ns < 2; ns++) {
            cc[ns] = fmaf(act[1][ns], cc[ns], act[0][ns] * act[2][ns]);
            float hn = act[3][ns] * tanhapx(cc[ns]);

            // pair h_j (even) with h_{j+1} (odd) via one shfl; even-j stores
            float hp = __shfl_xor_sync(0xffffffffu, hn, 4);
            if (!(gid & 1)) hsm[p ^ 1][n0 + ns][slot] = h2pack(hn, hp);
            if (t == TT - 1) hfin[n0 + ns][j] = hn;
        }

        if ((tid < 8) && (t + 1 < TT)) xs[p ^ 1][tid] = xpre;
        __syncthreads();
    }

    // ------------------- fused decoder (8 threads per CTA) -------------------
    if (tid < 8) {
        const float* he = hfin[tid];
        float z[4], wd[4];
        #pragma unroll
        for (int g = 0; g < 4; g++) {
            float acc = bih_d[g] + bhh_d[g];
            const float* wr = Wih_d + g * HH;
            #pragma unroll 8
            for (int k = 0; k < HH; k++) acc = fmaf(wr[k], he[k], acc);
            const float sd = (g == 2) ? 1.0f : 0.5f;
            z[g]  = sd * acc;
            wd[g] = sd * Whh_d[g];
        }
        float h = 0.0f, c = 0.0f;
        float* op = out + gbx;     // clamped dup races with identical values
        for (int t = 0; t < TT; t++) {
            float ai = fmaf(0.5f, tanhapx(fmaf(wd[0], h, z[0])), 0.5f);
            float af = fmaf(0.5f, tanhapx(fmaf(wd[1], h, z[1])), 0.5f);
            float ag = tanhapx(fmaf(wd[2], h, z[2]));
            float ao = fmaf(0.5f, tanhapx(fmaf(wd[3], h, z[3])), 0.5f);
            c = fmaf(af, c, ai * ag);
            h = ao * tanhapx(c);
            *op = h;
            op += BB;
        }
    }
}

// ---------------------------------------------------------------------------
// launch
// ---------------------------------------------------------------------------
extern "C" void kernel_launch(void* const* d_in, const int* in_sizes, int n_in,
                              void* d_out, int out_size) {
    const float* x     = (const float*)d_in[0];
    const float* Wih_e = (const float*)d_in[1];
    const float* Whh_e = (const float*)d_in[2];
    const float* bih_e = (const float*)d_in[3];
    const float* bhh_e = (const float*)d_in[4];
    const float* Wih_d = (const float*)d_in[5];
    const float* Whh_d = (const float*)d_in[6];
    const float* bih_d = (const float*)d_in[7];
    const float* bhh_d = (const float*)d_in[8];
    float* out = (float*)d_out;

    fused_kernel<<<CTAS, 256>>>(x, Wih_e, Whh_e, bih_e, bhh_e,
                                Wih_d, Whh_d, bih_d, bhh_d, out);
}